// round 3
// baseline (speedup 1.0000x reference)
#include <cuda_runtime.h>
#include <cstdint>
#include <cstddef>

// Problem constants
#define TT 512
#define BB 32
#define DD 512
#define HH 512

// ---------------------------------------------------------------------------
// Scratch (device globals — no allocations allowed)
// ---------------------------------------------------------------------------
// gi for one layer, both directions: [T*B][3072]  (dir-f cols 0..1535, dir-b 1536..3071)
__device__ float g_gi[(size_t)TT * BB * 3072];
// layer-0 output: [T][B][1024]
__device__ float g_y0[(size_t)TT * BB * 1024];
// hidden state ping-pong: 2 buffers of [2 dirs][512][32]  (k-major, batch-minor)
__device__ float g_h[2 * 2 * HH * BB];
// barrier state: arrival counters + release flags, one per direction
__device__ unsigned g_cnt[2];
__device__ unsigned g_flag[2];

// ---------------------------------------------------------------------------
// SGEMM (NT): C[m][n] = sum_k A[m][k] * W[n][k] + bias[n]
// A: [M][K] row-major, W: [N][K] row-major (both K-contiguous).
// BM=BN=128, BK=16, 256 threads, 8x8 microtile. M,N multiples of 128, K of 16.
// ---------------------------------------------------------------------------
__global__ void sgemm_nt_bias(const float* __restrict__ A,
                              const float* __restrict__ W,
                              const float* __restrict__ bias,
                              float* __restrict__ C,
                              int K, int ldc)
{
    __shared__ float As[16][128];
    __shared__ float Ws[16][128];

    const int tid = threadIdx.x;
    const int m0 = blockIdx.y * 128;
    const int n0 = blockIdx.x * 128;
    const int tx = tid & 15;   // n-dim
    const int ty = tid >> 4;   // m-dim

    float acc[8][8];
#pragma unroll
    for (int i = 0; i < 8; i++)
#pragma unroll
        for (int j = 0; j < 8; j++) acc[i][j] = 0.0f;

    const int lr = tid >> 2;         // 0..63
    const int lc = (tid & 3) * 4;    // 0,4,8,12

    for (int k0 = 0; k0 < K; k0 += 16) {
#pragma unroll
        for (int i = 0; i < 2; i++) {
            int r = lr + i * 64;
            float4 va = *(const float4*)(A + (size_t)(m0 + r) * K + k0 + lc);
            As[lc + 0][r] = va.x; As[lc + 1][r] = va.y;
            As[lc + 2][r] = va.z; As[lc + 3][r] = va.w;
            float4 vw = *(const float4*)(W + (size_t)(n0 + r) * K + k0 + lc);
            Ws[lc + 0][r] = vw.x; Ws[lc + 1][r] = vw.y;
            Ws[lc + 2][r] = vw.z; Ws[lc + 3][r] = vw.w;
        }
        __syncthreads();

#pragma unroll
        for (int k = 0; k < 16; k++) {
            float a[8], b[8];
#pragma unroll
            for (int i = 0; i < 8; i++) a[i] = As[k][ty * 8 + i];
#pragma unroll
            for (int j = 0; j < 8; j++) b[j] = Ws[k][tx * 8 + j];
#pragma unroll
            for (int i = 0; i < 8; i++)
#pragma unroll
                for (int j = 0; j < 8; j++) acc[i][j] += a[i] * b[j];
        }
        __syncthreads();
    }

    float bj[8];
#pragma unroll
    for (int j = 0; j < 8; j++) bj[j] = bias[n0 + tx * 8 + j];

#pragma unroll
    for (int i = 0; i < 8; i++) {
        float* crow = C + (size_t)(m0 + ty * 8 + i) * ldc + n0 + tx * 8;
        float4 v0, v1;
        v0.x = acc[i][0] + bj[0]; v0.y = acc[i][1] + bj[1];
        v0.z = acc[i][2] + bj[2]; v0.w = acc[i][3] + bj[3];
        v1.x = acc[i][4] + bj[4]; v1.y = acc[i][5] + bj[5];
        v1.z = acc[i][6] + bj[6]; v1.w = acc[i][7] + bj[7];
        *(float4*)(crow + 0) = v0;
        *(float4*)(crow + 4) = v1;
    }
}

// ---------------------------------------------------------------------------
// Persistent GRU layer kernel: ONE launch per layer, loops all 512 steps
// internally with a per-direction software grid barrier (counter + sense flag).
// Grid: 128 CTAs = 2 dirs x 64 j-blocks (JT=8). 256 threads (8 warps).
// Warp w -> j = j0+w, lane -> batch b. h layout: [buf][dir][k][b].
// Dynamic smem: hs[512*32] + ws[24*512] = 114688 B -> 1 CTA/SM, 128 <= 148 SMs
// so all CTAs are co-resident and the spin barrier cannot deadlock.
// ---------------------------------------------------------------------------
#define JT 8
#define NJB (HH / JT)   // 64 CTAs per direction
#define STEP_SMEM ((HH * BB + 3 * JT * HH) * (int)sizeof(float))

__global__ __launch_bounds__(256, 1)
void gru_layer_persistent(const float* __restrict__ gi,
                          const float* __restrict__ Whh_f,
                          const float* __restrict__ Whh_b,
                          const float* __restrict__ bhh_f,
                          const float* __restrict__ bhh_b,
                          float* __restrict__ hbuf,    // [2][2][HH][BB]
                          unsigned* __restrict__ cnt,  // [2], zeroed pre-launch
                          unsigned* __restrict__ flag, // [2], zeroed pre-launch
                          float* __restrict__ y,       // [T][B][1024]
                          float* __restrict__ hid)     // [2][B][H]
{
    extern __shared__ float sm[];
    float* hs = sm;                  // [512][32]
    float* ws = sm + HH * BB;        // [24][512]

    const int tid = threadIdx.x;
    const int dir = blockIdx.x >> 6;       // / NJB
    const int jb  = blockIdx.x & (NJB - 1);
    const int j0  = jb * JT;

    const float* Whh = dir ? Whh_b : Whh_f;
    const float* bhh = dir ? bhh_b : bhh_f;

    // Stage Whh rows (3 gates x 8 j) ONCE for all 512 steps: 3072 float4.
    {
        float4* dst = (float4*)ws;
#pragma unroll
        for (int i = 0; i < 12; i++) {
            int idx = tid + i * 256;
            int rr  = idx >> 7;          // 0..23
            int c   = idx & 127;         // float4 col
            int g   = rr >> 3;
            int jj  = j0 + (rr & 7);
            dst[idx] = *(const float4*)(Whh + (size_t)(g * HH + jj) * HH + c * 4);
        }
    }

    const int w    = tid >> 5;
    const int lane = tid & 31;
    const int j    = j0 + w;
    const int b    = lane;

    const float br = bhh[j];
    const float bz = bhh[HH + j];
    const float bn = bhh[2 * HH + j];

    const float* wr = ws + (0 * JT + w) * HH;
    const float* wz = ws + (1 * JT + w) * HH;
    const float* wn = ws + (2 * JT + w) * HH;

    unsigned* mycnt  = cnt + dir;
    unsigned* myflag = flag + dir;
    const size_t dslab = (size_t)HH * BB;

    for (int s = 0; s < TT; s++) {
        // ---- stage h for this step (bypass L1: written by other SMs) ----
        const float4* src = (const float4*)(hbuf + ((size_t)(s & 1) * 2 + dir) * dslab);
        float4* hd = (float4*)hs;
#pragma unroll
        for (int i = 0; i < 16; i++) {
            int idx = tid + i * 256;
            hd[idx] = __ldcg(src + idx);
        }
        __syncthreads();

        // issue the gi loads early (they are independent of the matvec)
        const int t = dir ? (TT - 1 - s) : s;
        const size_t gbase = ((size_t)t * BB + b) * 3072 + (size_t)dir * 1536;
        const float ir  = __ldcg(gi + gbase + j);
        const float iz  = __ldcg(gi + gbase + HH + j);
        const float inn = __ldcg(gi + gbase + 2 * HH + j);

        // ---- recurrent matvec for (j, b) over k ----
        float ar = 0.0f, az = 0.0f, an = 0.0f;
#pragma unroll 8
        for (int k = 0; k < HH; k += 4) {
            const float4 r4 = *(const float4*)(wr + k);
            const float4 z4 = *(const float4*)(wz + k);
            const float4 n4 = *(const float4*)(wn + k);
            const float* hk = hs + k * BB + lane;
            const float h0 = hk[0];
            const float h1 = hk[BB];
            const float h2 = hk[2 * BB];
            const float h3 = hk[3 * BB];
            ar += r4.x * h0; az += z4.x * h0; an += n4.x * h0;
            ar += r4.y * h1; az += z4.y * h1; an += n4.y * h1;
            ar += r4.z * h2; az += z4.z * h2; an += n4.z * h2;
            ar += r4.w * h3; az += z4.w * h3; an += n4.w * h3;
        }
        ar += br; az += bz; an += bn;

        const float r = 1.0f / (1.0f + expf(-(ir + ar)));
        const float z = 1.0f / (1.0f + expf(-(iz + az)));
        const float n = tanhf(inn + r * an);
        const float hp = hs[j * BB + b];
        const float hn = (1.0f - z) * n + z * hp;

        hbuf[((size_t)((s + 1) & 1) * 2 + dir) * dslab + j * BB + b] = hn;
        y[((size_t)t * BB + b) * 1024 + (size_t)dir * HH + j] = hn;
        if (s == TT - 1) {
            hid[((size_t)dir * BB + b) * HH + j] = hn;
        }

        // ---- per-direction grid barrier: counter + sense flag ----
        __syncthreads();       // all threads of CTA done (h stores + hs reads)
        if (tid == 0) {
            __threadfence();   // publish this CTA's h stores device-wide
            const unsigned target = (unsigned)(NJB * (s + 1));
            unsigned arrived = atomicAdd(mycnt, 1u) + 1u;
            if (arrived == target) {
                // last arriver: release all spinners
                asm volatile("st.release.gpu.global.u32 [%0], %1;"
                             :: "l"(myflag), "r"((unsigned)(s + 1)) : "memory");
            } else {
                unsigned v;
                do {
                    asm volatile("ld.acquire.gpu.global.u32 %0, [%1];"
                                 : "=r"(v) : "l"(myflag) : "memory");
                } while (v < (unsigned)(s + 1));
            }
            __threadfence();   // acquire: order subsequent h reads after barrier
        }
        __syncthreads();
    }
}

// ---------------------------------------------------------------------------
// Launch
// ---------------------------------------------------------------------------
extern "C" void kernel_launch(void* const* d_in, const int* in_sizes, int n_in,
                              void* d_out, int out_size)
{
    (void)in_sizes; (void)n_in; (void)out_size;

    const float* x     = (const float*)d_in[0];
    const float* Wih0f = (const float*)d_in[1];
    const float* Whh0f = (const float*)d_in[2];
    const float* bih0f = (const float*)d_in[3];
    const float* bhh0f = (const float*)d_in[4];
    const float* Wih0b = (const float*)d_in[5];
    const float* Whh0b = (const float*)d_in[6];
    const float* bih0b = (const float*)d_in[7];
    const float* bhh0b = (const float*)d_in[8];
    const float* Wih1f = (const float*)d_in[9];
    const float* Whh1f = (const float*)d_in[10];
    const float* bih1f = (const float*)d_in[11];
    const float* bhh1f = (const float*)d_in[12];
    const float* Wih1b = (const float*)d_in[13];
    const float* Whh1b = (const float*)d_in[14];
    const float* bih1b = (const float*)d_in[15];
    const float* bhh1b = (const float*)d_in[16];

    float* out = (float*)d_out;
    const size_t Y_ELEMS = (size_t)TT * BB * 1024;
    float* hid0 = out + Y_ELEMS;                 // [2][B][H] layer0 f,b
    float* hid1 = out + Y_ELEMS + 2 * BB * HH;   // [2][B][H] layer1 f,b

    float* gi = nullptr; cudaGetSymbolAddress((void**)&gi, g_gi);
    float* y0 = nullptr; cudaGetSymbolAddress((void**)&y0, g_y0);
    float* hb = nullptr; cudaGetSymbolAddress((void**)&hb, g_h);
    unsigned* cnt  = nullptr; cudaGetSymbolAddress((void**)&cnt, g_cnt);
    unsigned* flag = nullptr; cudaGetSymbolAddress((void**)&flag, g_flag);

    cudaFuncSetAttribute(gru_layer_persistent,
                         cudaFuncAttributeMaxDynamicSharedMemorySize, STEP_SMEM);

    const dim3 ggrid(1536 / 128, (TT * BB) / 128);  // (12, 128)

    // ---------------- layer 0 ----------------
    sgemm_nt_bias<<<ggrid, 256>>>(x, Wih0f, bih0f, gi,        DD, 3072);
    sgemm_nt_bias<<<ggrid, 256>>>(x, Wih0b, bih0b, gi + 1536, DD, 3072);

    cudaMemsetAsync(hb, 0, (size_t)2 * HH * BB * sizeof(float)); // h0 = 0 (buf 0)
    cudaMemsetAsync(cnt, 0, 2 * sizeof(unsigned));
    cudaMemsetAsync(flag, 0, 2 * sizeof(unsigned));

    gru_layer_persistent<<<2 * NJB, 256, STEP_SMEM>>>(
        gi, Whh0f, Whh0b, bhh0f, bhh0b, hb, cnt, flag, y0, hid0);

    // ---------------- layer 1 ----------------
    sgemm_nt_bias<<<ggrid, 256>>>(y0, Wih1f, bih1f, gi,        2 * HH, 3072);
    sgemm_nt_bias<<<ggrid, 256>>>(y0, Wih1b, bih1b, gi + 1536, 2 * HH, 3072);

    cudaMemsetAsync(hb, 0, (size_t)2 * HH * BB * sizeof(float));
    cudaMemsetAsync(cnt, 0, 2 * sizeof(unsigned));
    cudaMemsetAsync(flag, 0, 2 * sizeof(unsigned));

    gru_layer_persistent<<<2 * NJB, 256, STEP_SMEM>>>(
        gi, Whh1f, Whh1b, bhh1f, bhh1b, hb, cnt, flag, out, hid1);
}

// round 4
// speedup vs baseline: 1.0777x; 1.0777x over previous
#include <cuda_runtime.h>
#include <cstdint>
#include <cstddef>

typedef unsigned long long ull;

// Problem constants
#define TT 512
#define BB 32
#define DD 512
#define HH 512

// ---------------------------------------------------------------------------
// Scratch (device globals — no allocations allowed)
// ---------------------------------------------------------------------------
// gi TRANSPOSED: [dir][gate*512+j][t*32+b]  (m = t*32+b contiguous, ld = 16384)
__device__ float g_gi[(size_t)2 * 1536 * (TT * BB)];
// layer-0 output: [T][B][1024]
__device__ float g_y0[(size_t)TT * BB * 1024];
// hidden state ping-pong: 2 buffers of [2 dirs][512 j][32 b]
__device__ float g_h[2 * 2 * HH * BB];
// barrier state: arrival counters + release flags, one per direction
__device__ unsigned g_cnt[2];
__device__ unsigned g_flag[2];

// ---------------------------------------------------------------------------
// FFMA2 GEMM (TN-ish): C[n][m] = sum_k Wn[n][k] * Xm[m][k] + bias[n]
// Wn: [N][K] row-major (weights), Xm: [M][K] row-major (activations).
// C row-major with ldc = M (m contiguous!).
// BN=BM=128, BK=16, 256 threads. Thread microtile: 8 n-rows x 8 m-cols,
// m-cols processed as 4 adjacent PAIRS via fma.rn.f32x2 (packed fp32x2).
//   - W operand duplicated in smem (Asd[k][2r]=Asd[k][2r+1]=w) -> 64-bit
//     splat loads (broadcast, conflict-free).
//   - X operand natural adjacent pairs: thread tx owns m-pairs {tx+16*pp},
//     i.e. columns {2*(tx+16pp), +1}: LDS.64 stride 8B -> conflict-free.
// ---------------------------------------------------------------------------
__global__ void sgemm_tn_ffma2(const float* __restrict__ Wn,
                               const float* __restrict__ Xm,
                               const float* __restrict__ bias,
                               float* __restrict__ C,
                               int K, int ldc)
{
    __shared__ float Asd[16][256];   // duplicated W tile: [k][2*r(+dup)]
    __shared__ float Ws[16][128];    // X tile: [k][m-col]

    const int tid = threadIdx.x;
    const int n0 = blockIdx.y * 128;
    const int m0 = blockIdx.x * 128;
    const int tx = tid & 15;   // m-pair group
    const int ty = tid >> 4;   // n-dim

    ull acc[8][4];
#pragma unroll
    for (int i = 0; i < 8; i++)
#pragma unroll
        for (int p = 0; p < 4; p++) acc[i][p] = 0ULL;

    const int lr = tid >> 2;         // 0..63
    const int lc = (tid & 3) * 4;    // 0,4,8,12

    for (int k0 = 0; k0 < K; k0 += 16) {
#pragma unroll
        for (int i = 0; i < 2; i++) {
            int r = lr + i * 64;
            float4 vw = *(const float4*)(Wn + (size_t)(n0 + r) * K + k0 + lc);
            Asd[lc + 0][2 * r] = vw.x; Asd[lc + 0][2 * r + 1] = vw.x;
            Asd[lc + 1][2 * r] = vw.y; Asd[lc + 1][2 * r + 1] = vw.y;
            Asd[lc + 2][2 * r] = vw.z; Asd[lc + 2][2 * r + 1] = vw.z;
            Asd[lc + 3][2 * r] = vw.w; Asd[lc + 3][2 * r + 1] = vw.w;
            float4 vx = *(const float4*)(Xm + (size_t)(m0 + r) * K + k0 + lc);
            Ws[lc + 0][r] = vx.x; Ws[lc + 1][r] = vx.y;
            Ws[lc + 2][r] = vx.z; Ws[lc + 3][r] = vx.w;
        }
        __syncthreads();

#pragma unroll
        for (int k = 0; k < 16; k++) {
            const ull* ad = (const ull*)&Asd[k][0];  // ull index = float/2
            const ull* bd = (const ull*)&Ws[k][0];
            ull a[8], b[4];
#pragma unroll
            for (int i = 0; i < 8; i++) a[i] = ad[ty * 8 + i];   // splat (w,w)
#pragma unroll
            for (int p = 0; p < 4; p++) b[p] = bd[tx + 16 * p];  // pair (x0,x1)
#pragma unroll
            for (int i = 0; i < 8; i++)
#pragma unroll
                for (int p = 0; p < 4; p++)
                    asm("fma.rn.f32x2 %0, %1, %2, %0;"
                        : "+l"(acc[i][p]) : "l"(a[i]), "l"(b[p]));
        }
        __syncthreads();
    }

#pragma unroll
    for (int i = 0; i < 8; i++) {
        const int n = n0 + ty * 8 + i;
        const float bi = bias[n];
#pragma unroll
        for (int p = 0; p < 4; p++) {
            float lo = __uint_as_float((unsigned)(acc[i][p] & 0xFFFFFFFFu)) + bi;
            float hi = __uint_as_float((unsigned)(acc[i][p] >> 32)) + bi;
            float2 v; v.x = lo; v.y = hi;
            *(float2*)(C + (size_t)n * ldc + m0 + 2 * (tx + 16 * p)) = v;
        }
    }
}

// ---------------------------------------------------------------------------
// Persistent GRU layer kernel: ONE launch per layer, loops all 512 steps
// internally with a per-direction software grid barrier (counter + sense flag).
// Grid: 128 CTAs = 2 dirs x 64 j-blocks (JT=8). 256 threads (8 warps).
// Warp w -> j = j0+w, lane -> batch b. h layout: [buf][dir][j][b].
// gi is TRANSPOSED: [dir][gate*512+j][t*32+b] -> coalesced lane-b loads.
// Dynamic smem: hs[512*32] + ws[24*512] = 114688 B -> 1 CTA/SM, 128 <= 148 SMs
// so all CTAs are co-resident and the spin barrier cannot deadlock.
// ---------------------------------------------------------------------------
#define JT 8
#define NJB (HH / JT)   // 64 CTAs per direction
#define STEP_SMEM ((HH * BB + 3 * JT * HH) * (int)sizeof(float))

__global__ __launch_bounds__(256, 1)
void gru_layer_persistent(const float* __restrict__ gi,
                          const float* __restrict__ Whh_f,
                          const float* __restrict__ Whh_b,
                          const float* __restrict__ bhh_f,
                          const float* __restrict__ bhh_b,
                          float* __restrict__ hbuf,    // [2][2][HH][BB]
                          unsigned* __restrict__ cnt,  // [2], zeroed pre-launch
                          unsigned* __restrict__ flag, // [2], zeroed pre-launch
                          float* __restrict__ y,       // [T][B][1024]
                          float* __restrict__ hid)     // [2][B][H]
{
    extern __shared__ float sm[];
    float* hs = sm;                  // [512][32]
    float* ws = sm + HH * BB;        // [24][512]

    const int tid = threadIdx.x;
    const int dir = blockIdx.x >> 6;       // / NJB
    const int jb  = blockIdx.x & (NJB - 1);
    const int j0  = jb * JT;

    const float* Whh = dir ? Whh_b : Whh_f;
    const float* bhh = dir ? bhh_b : bhh_f;

    // Stage Whh rows (3 gates x 8 j) ONCE for all 512 steps: 3072 float4.
    {
        float4* dst = (float4*)ws;
#pragma unroll
        for (int i = 0; i < 12; i++) {
            int idx = tid + i * 256;
            int rr  = idx >> 7;          // 0..23
            int c   = idx & 127;         // float4 col
            int g   = rr >> 3;
            int jj  = j0 + (rr & 7);
            dst[idx] = *(const float4*)(Whh + (size_t)(g * HH + jj) * HH + c * 4);
        }
    }

    const int w    = tid >> 5;
    const int lane = tid & 31;
    const int j    = j0 + w;
    const int b    = lane;

    const float br = bhh[j];
    const float bz = bhh[HH + j];
    const float bn = bhh[2 * HH + j];

    const float* wr = ws + (0 * JT + w) * HH;
    const float* wz = ws + (1 * JT + w) * HH;
    const float* wn = ws + (2 * JT + w) * HH;

    // transposed-gi base pointers for this (dir, j, b): offset per step = t*32
    const float* gir = gi + ((size_t)dir * 1536 + 0 * HH + j) * (TT * BB) + b;
    const float* giz = gi + ((size_t)dir * 1536 + 1 * HH + j) * (TT * BB) + b;
    const float* gin = gi + ((size_t)dir * 1536 + 2 * HH + j) * (TT * BB) + b;

    unsigned* mycnt  = cnt + dir;
    unsigned* myflag = flag + dir;
    const size_t dslab = (size_t)HH * BB;

    // prefetch gi for step 0
    int t = dir ? (TT - 1) : 0;
    float ir  = __ldcg(gir + t * BB);
    float iz  = __ldcg(giz + t * BB);
    float inn = __ldcg(gin + t * BB);

    for (int s = 0; s < TT; s++) {
        // ---- stage h for this step (bypass L1: written by other SMs) ----
        const float4* src = (const float4*)(hbuf + ((size_t)(s & 1) * 2 + dir) * dslab);
        float4* hd = (float4*)hs;
#pragma unroll
        for (int i = 0; i < 16; i++) {
            int idx = tid + i * 256;
            hd[idx] = __ldcg(src + idx);
        }
        __syncthreads();

        // ---- recurrent matvec for (j, b) over k ----
        float ar = 0.0f, az = 0.0f, an = 0.0f;
#pragma unroll 8
        for (int k = 0; k < HH; k += 4) {
            const float4 r4 = *(const float4*)(wr + k);
            const float4 z4 = *(const float4*)(wz + k);
            const float4 n4 = *(const float4*)(wn + k);
            const float* hk = hs + k * BB + lane;
            const float h0 = hk[0];
            const float h1 = hk[BB];
            const float h2 = hk[2 * BB];
            const float h3 = hk[3 * BB];
            ar += r4.x * h0; az += z4.x * h0; an += n4.x * h0;
            ar += r4.y * h1; az += z4.y * h1; an += n4.y * h1;
            ar += r4.z * h2; az += z4.z * h2; an += n4.z * h2;
            ar += r4.w * h3; az += z4.w * h3; an += n4.w * h3;
        }
        ar += br; az += bz; an += bn;

        const float r = 1.0f / (1.0f + expf(-(ir + ar)));
        const float z = 1.0f / (1.0f + expf(-(iz + az)));
        const float n = tanhf(inn + r * an);
        const float hp = hs[j * BB + b];
        const float hn = (1.0f - z) * n + z * hp;

        // critical-path store first: next step's h
        hbuf[((size_t)((s + 1) & 1) * 2 + dir) * dslab + j * BB + b] = hn;

        // ---- per-direction grid barrier: counter + sense flag ----
        __syncthreads();       // all threads' h stores issued
        if (tid == 0) {
            __threadfence();   // publish this CTA's h stores device-wide
            const unsigned target = (unsigned)(NJB * (s + 1));
            unsigned arrived = atomicAdd(mycnt, 1u) + 1u;
            if (arrived == target) {
                asm volatile("st.release.gpu.global.u32 [%0], %1;"
                             :: "l"(myflag), "r"((unsigned)(s + 1)) : "memory");
            }
        }

        // off-critical-path work while tid0 spins / others before final sync:
        y[((size_t)t * BB + b) * 1024 + (size_t)dir * HH + j] = hn;
        if (s == TT - 1) {
            hid[((size_t)dir * BB + b) * HH + j] = hn;
        } else {
            // prefetch gi for step s+1
            const int tn = dir ? (TT - 2 - s) : (s + 1);
            ir  = __ldcg(gir + tn * BB);
            iz  = __ldcg(giz + tn * BB);
            inn = __ldcg(gin + tn * BB);
            t = tn;
        }

        if (tid == 0) {
            unsigned v;
            do {
                asm volatile("ld.acquire.gpu.global.u32 %0, [%1];"
                             : "=r"(v) : "l"(myflag) : "memory");
            } while (v < (unsigned)(s + 1));
            __threadfence();
        }
        __syncthreads();
    }
}

// ---------------------------------------------------------------------------
// Launch
// ---------------------------------------------------------------------------
extern "C" void kernel_launch(void* const* d_in, const int* in_sizes, int n_in,
                              void* d_out, int out_size)
{
    (void)in_sizes; (void)n_in; (void)out_size;

    const float* x     = (const float*)d_in[0];
    const float* Wih0f = (const float*)d_in[1];
    const float* Whh0f = (const float*)d_in[2];
    const float* bih0f = (const float*)d_in[3];
    const float* bhh0f = (const float*)d_in[4];
    const float* Wih0b = (const float*)d_in[5];
    const float* Whh0b = (const float*)d_in[6];
    const float* bih0b = (const float*)d_in[7];
    const float* bhh0b = (const float*)d_in[8];
    const float* Wih1f = (const float*)d_in[9];
    const float* Whh1f = (const float*)d_in[10];
    const float* bih1f = (const float*)d_in[11];
    const float* bhh1f = (const float*)d_in[12];
    const float* Wih1b = (const float*)d_in[13];
    const float* Whh1b = (const float*)d_in[14];
    const float* bih1b = (const float*)d_in[15];
    const float* bhh1b = (const float*)d_in[16];

    float* out = (float*)d_out;
    const size_t Y_ELEMS = (size_t)TT * BB * 1024;
    float* hid0 = out + Y_ELEMS;                 // [2][B][H] layer0 f,b
    float* hid1 = out + Y_ELEMS + 2 * BB * HH;   // [2][B][H] layer1 f,b

    float* gi = nullptr; cudaGetSymbolAddress((void**)&gi, g_gi);
    float* y0 = nullptr; cudaGetSymbolAddress((void**)&y0, g_y0);
    float* hb = nullptr; cudaGetSymbolAddress((void**)&hb, g_h);
    unsigned* cnt  = nullptr; cudaGetSymbolAddress((void**)&cnt, g_cnt);
    unsigned* flag = nullptr; cudaGetSymbolAddress((void**)&flag, g_flag);

    cudaFuncSetAttribute(gru_layer_persistent,
                         cudaFuncAttributeMaxDynamicSharedMemorySize, STEP_SMEM);

    const size_t M = (size_t)TT * BB;            // 16384
    const size_t DIROFF = (size_t)1536 * M;      // dir-b slab offset in gi
    const dim3 ggrid(128, 12);                   // (m-tiles, n-tiles)

    // ---------------- layer 0 ----------------
    sgemm_tn_ffma2<<<ggrid, 256>>>(Wih0f, x, bih0f, gi,          DD, (int)M);
    sgemm_tn_ffma2<<<ggrid, 256>>>(Wih0b, x, bih0b, gi + DIROFF, DD, (int)M);

    cudaMemsetAsync(hb, 0, (size_t)2 * HH * BB * sizeof(float)); // h0 = 0 (buf 0)
    cudaMemsetAsync(cnt, 0, 2 * sizeof(unsigned));
    cudaMemsetAsync(flag, 0, 2 * sizeof(unsigned));

    gru_layer_persistent<<<2 * NJB, 256, STEP_SMEM>>>(
        gi, Whh0f, Whh0b, bhh0f, bhh0b, hb, cnt, flag, y0, hid0);

    // ---------------- layer 1 ----------------
    sgemm_tn_ffma2<<<ggrid, 256>>>(Wih1f, y0, bih1f, gi,          2 * HH, (int)M);
    sgemm_tn_ffma2<<<ggrid, 256>>>(Wih1b, y0, bih1b, gi + DIROFF, 2 * HH, (int)M);

    cudaMemsetAsync(hb, 0, (size_t)2 * HH * BB * sizeof(float));
    cudaMemsetAsync(cnt, 0, 2 * sizeof(unsigned));
    cudaMemsetAsync(flag, 0, 2 * sizeof(unsigned));

    gru_layer_persistent<<<2 * NJB, 256, STEP_SMEM>>>(
        gi, Whh1f, Whh1b, bhh1f, bhh1b, hb, cnt, flag, out, hid1);
}

// round 6
// speedup vs baseline: 1.2881x; 1.1952x over previous
#include <cuda_runtime.h>
#include <cuda_bf16.h>
#include <cstdint>
#include <cstddef>

typedef unsigned long long ull;

// Problem constants
#define TT 512
#define BB 32
#define DD 512
#define HH 512

// ---------------------------------------------------------------------------
// Scratch (device globals — no allocations allowed)
// ---------------------------------------------------------------------------
// gi TRANSPOSED: [dir][gate*512+j][t*32+b]  (m = t*32+b contiguous, ld = 16384)
__device__ float g_gi[(size_t)2 * 1536 * (TT * BB)];
// layer-0 output: [T][B][1024]
__device__ float g_y0[(size_t)TT * BB * 1024];
// hidden state ping-pong: 2 buffers of [2 dirs][512 j][32 b]
__device__ float g_h[2 * 2 * HH * BB];
// barrier state
__device__ unsigned g_cnt[2];
__device__ unsigned g_flag[2];
// bf16 split operands (hi/lo) for tensor-core GEMMs
__device__ __nv_bfloat16 g_wh[2][1536 * 1024];        // W hi, per dir
__device__ __nv_bfloat16 g_wl[2][1536 * 1024];        // W lo, per dir
__device__ __nv_bfloat16 g_xh[(size_t)16384 * 1024];  // X hi
__device__ __nv_bfloat16 g_xl[(size_t)16384 * 1024];  // X lo

// ---------------------------------------------------------------------------
// split fp32 -> bf16 hi + bf16 lo
// ---------------------------------------------------------------------------
__global__ void split_bf16(const float* __restrict__ x,
                           __nv_bfloat16* __restrict__ hi,
                           __nv_bfloat16* __restrict__ lo, size_t n)
{
    size_t i = (size_t)blockIdx.x * blockDim.x + threadIdx.x;
    size_t stride = (size_t)gridDim.x * blockDim.x;
    for (; i < n; i += stride) {
        float v = x[i];
        __nv_bfloat16 h = __float2bfloat16(v);
        hi[i] = h;
        lo[i] = __float2bfloat16(v - __bfloat162float(h));
    }
}

// ---------------------------------------------------------------------------
// bf16 mma.sync GEMM, 3-pass hi/lo split, fp32 accumulate.
// C[n][m] = sum_k W[n][k] * X[m][k] + bias[n],  ldc = M = 16384.
// Grid (m_tiles=128, n_tiles), 256 threads (8 warps, 2x4 layout).
// CTA tile: 128(n) x 128(m) x BK=32. Warp tile: 64(n) x 32(m).
// mma.sync.aligned.m16n8k16.row.col.f32.bf16.bf16.f32:
//   A = W rows (row-major, k contig), B = X rows (= B^T, ldmatrix non-trans).
// SMEM padded stride 40 bf16 (80 B): ldmatrix rows hit banks {20r mod 32},
// conflict-free; 80 B is a multiple of 16 B so uint4/ldmatrix alignment holds.
// ---------------------------------------------------------------------------
#define SKW 40

#define MMA_BF16(d, a, b) \
    asm volatile("mma.sync.aligned.m16n8k16.row.col.f32.bf16.bf16.f32 " \
        "{%0,%1,%2,%3}, {%4,%5,%6,%7}, {%8,%9}, {%0,%1,%2,%3};" \
        : "+f"((d)[0]), "+f"((d)[1]), "+f"((d)[2]), "+f"((d)[3]) \
        : "r"((a)[0]), "r"((a)[1]), "r"((a)[2]), "r"((a)[3]), \
          "r"((b)[0]), "r"((b)[1]))

#define LDSM_X4(r, addr) \
    asm volatile("ldmatrix.sync.aligned.m8n8.x4.shared.b16 {%0,%1,%2,%3}, [%4];" \
        : "=r"((r)[0]), "=r"((r)[1]), "=r"((r)[2]), "=r"((r)[3]) : "r"(addr))

#define LDSM_X2(r, addr) \
    asm volatile("ldmatrix.sync.aligned.m8n8.x2.shared.b16 {%0,%1}, [%2];" \
        : "=r"((r)[0]), "=r"((r)[1]) : "r"(addr))

__global__ void __launch_bounds__(256)
gemm_bf16_mma(const __nv_bfloat16* __restrict__ Wh,
              const __nv_bfloat16* __restrict__ Wl,
              const __nv_bfloat16* __restrict__ Xh,
              const __nv_bfloat16* __restrict__ Xl,
              const float* __restrict__ bias,
              float* __restrict__ C, int K, int ldc)
{
    __shared__ __align__(16) __nv_bfloat16 sWh[128 * SKW];
    __shared__ __align__(16) __nv_bfloat16 sWl[128 * SKW];
    __shared__ __align__(16) __nv_bfloat16 sXh[128 * SKW];
    __shared__ __align__(16) __nv_bfloat16 sXl[128 * SKW];

    const int tid  = threadIdx.x;
    const int wid  = tid >> 5;
    const int lane = tid & 31;
    const int m0   = blockIdx.x * 128;
    const int n0   = blockIdx.y * 128;
    const int wn   = wid >> 2;   // 0..1 (n)
    const int wm   = wid & 3;    // 0..3 (m)

    float acc[4][4][4];
#pragma unroll
    for (int nt = 0; nt < 4; nt++)
#pragma unroll
        for (int mt = 0; mt < 4; mt++)
#pragma unroll
            for (int e = 0; e < 4; e++) acc[nt][mt][e] = 0.0f;

    // ldmatrix smem addresses (per-lane), computed once
    const int a_row = wn * 64 + (lane & 15);
    const int a_col = (lane >> 4) * 8;
    const int b_row = wm * 32 + (lane & 7);
    const int b_col = ((lane >> 3) & 1) * 8;
    uint32_t aWh = (uint32_t)__cvta_generic_to_shared(&sWh[a_row * SKW + a_col]);
    uint32_t aWl = (uint32_t)__cvta_generic_to_shared(&sWl[a_row * SKW + a_col]);
    uint32_t aXh = (uint32_t)__cvta_generic_to_shared(&sXh[b_row * SKW + b_col]);
    uint32_t aXl = (uint32_t)__cvta_generic_to_shared(&sXl[b_row * SKW + b_col]);

    for (int k0 = 0; k0 < K; k0 += 32) {
        // ---- stage 4 tiles: 128 rows x 4 uint4 chunks each ----
#pragma unroll
        for (int i = 0; i < 2; i++) {
            int idx = tid + i * 256;       // 0..511
            int row = idx >> 2;
            int c   = idx & 3;
            int so  = row * SKW + c * 8;
            size_t gw = (size_t)(n0 + row) * K + k0 + c * 8;
            size_t gx = (size_t)(m0 + row) * K + k0 + c * 8;
            *(uint4*)&sWh[so] = *(const uint4*)(Wh + gw);
            *(uint4*)&sWl[so] = *(const uint4*)(Wl + gw);
            *(uint4*)&sXh[so] = *(const uint4*)(Xh + gx);
            *(uint4*)&sXl[so] = *(const uint4*)(Xl + gx);
        }
        __syncthreads();

#pragma unroll
        for (int kk = 0; kk < 2; kk++) {
            const uint32_t koff = (uint32_t)(kk * 16 * 2);  // bytes
            uint32_t ah[4][4], al[4][4], bh[4][2], bl[4][2];
#pragma unroll
            for (int nt = 0; nt < 4; nt++) {
                const uint32_t ro = (uint32_t)(nt * 16 * SKW * 2);
                LDSM_X4(ah[nt], aWh + ro + koff);
                LDSM_X4(al[nt], aWl + ro + koff);
            }
#pragma unroll
            for (int mt = 0; mt < 4; mt++) {
                const uint32_t ro = (uint32_t)(mt * 8 * SKW * 2);
                LDSM_X2(bh[mt], aXh + ro + koff);
                LDSM_X2(bl[mt], aXl + ro + koff);
            }
#pragma unroll
            for (int nt = 0; nt < 4; nt++)
#pragma unroll
                for (int mt = 0; mt < 4; mt++) {
                    MMA_BF16(acc[nt][mt], ah[nt], bh[mt]);
                    MMA_BF16(acc[nt][mt], ah[nt], bl[mt]);
                    MMA_BF16(acc[nt][mt], al[nt], bh[mt]);
                }
        }
        __syncthreads();
    }

    // ---- epilogue: add bias, write float2 pairs ----
    const int r0 = lane >> 2;
    const int c0 = (lane & 3) * 2;
#pragma unroll
    for (int nt = 0; nt < 4; nt++) {
        const int nbase = n0 + wn * 64 + nt * 16;
        const float b0 = bias[nbase + r0];
        const float b1 = bias[nbase + 8 + r0];
#pragma unroll
        for (int mt = 0; mt < 4; mt++) {
            const int mbase = m0 + wm * 32 + mt * 8;
            float2 v0, v1;
            v0.x = acc[nt][mt][0] + b0; v0.y = acc[nt][mt][1] + b0;
            v1.x = acc[nt][mt][2] + b1; v1.y = acc[nt][mt][3] + b1;
            *(float2*)(C + (size_t)(nbase + r0) * ldc + mbase + c0) = v0;
            *(float2*)(C + (size_t)(nbase + 8 + r0) * ldc + mbase + c0) = v1;
        }
    }
}

// ---------------------------------------------------------------------------
// Persistent GRU layer kernel (unchanged from round 4 pass)
// ---------------------------------------------------------------------------
#define JT 8
#define NJB (HH / JT)
#define STEP_SMEM ((HH * BB + 3 * JT * HH) * (int)sizeof(float))

__global__ __launch_bounds__(256, 1)
void gru_layer_persistent(const float* __restrict__ gi,
                          const float* __restrict__ Whh_f,
                          const float* __restrict__ Whh_b,
                          const float* __restrict__ bhh_f,
                          const float* __restrict__ bhh_b,
                          float* __restrict__ hbuf,
                          unsigned* __restrict__ cnt,
                          unsigned* __restrict__ flag,
                          float* __restrict__ y,
                          float* __restrict__ hid)
{
    extern __shared__ float sm[];
    float* hs = sm;                  // [512][32]
    float* ws = sm + HH * BB;        // [24][512]

    const int tid = threadIdx.x;
    const int dir = blockIdx.x >> 6;
    const int jb  = blockIdx.x & (NJB - 1);
    const int j0  = jb * JT;

    const float* Whh = dir ? Whh_b : Whh_f;
    const float* bhh = dir ? bhh_b : bhh_f;

    {
        float4* dst = (float4*)ws;
#pragma unroll
        for (int i = 0; i < 12; i++) {
            int idx = tid + i * 256;
            int rr  = idx >> 7;
            int c   = idx & 127;
            int g   = rr >> 3;
            int jj  = j0 + (rr & 7);
            dst[idx] = *(const float4*)(Whh + (size_t)(g * HH + jj) * HH + c * 4);
        }
    }

    const int w    = tid >> 5;
    const int lane = tid & 31;
    const int j    = j0 + w;
    const int b    = lane;

    const float br = bhh[j];
    const float bz = bhh[HH + j];
    const float bn = bhh[2 * HH + j];

    const float* wr = ws + (0 * JT + w) * HH;
    const float* wz = ws + (1 * JT + w) * HH;
    const float* wn = ws + (2 * JT + w) * HH;

    const float* gir = gi + ((size_t)dir * 1536 + 0 * HH + j) * (TT * BB) + b;
    const float* giz = gi + ((size_t)dir * 1536 + 1 * HH + j) * (TT * BB) + b;
    const float* gin = gi + ((size_t)dir * 1536 + 2 * HH + j) * (TT * BB) + b;

    unsigned* mycnt  = cnt + dir;
    unsigned* myflag = flag + dir;
    const size_t dslab = (size_t)HH * BB;

    int t = dir ? (TT - 1) : 0;
    float ir  = __ldcg(gir + t * BB);
    float iz  = __ldcg(giz + t * BB);
    float inn = __ldcg(gin + t * BB);

    for (int s = 0; s < TT; s++) {
        const float4* src = (const float4*)(hbuf + ((size_t)(s & 1) * 2 + dir) * dslab);
        float4* hd = (float4*)hs;
#pragma unroll
        for (int i = 0; i < 16; i++) {
            int idx = tid + i * 256;
            hd[idx] = __ldcg(src + idx);
        }
        __syncthreads();

        float ar = 0.0f, az = 0.0f, an = 0.0f;
#pragma unroll 8
        for (int k = 0; k < HH; k += 4) {
            const float4 r4 = *(const float4*)(wr + k);
            const float4 z4 = *(const float4*)(wz + k);
            const float4 n4 = *(const float4*)(wn + k);
            const float* hk = hs + k * BB + lane;
            const float h0 = hk[0];
            const float h1 = hk[BB];
            const float h2 = hk[2 * BB];
            const float h3 = hk[3 * BB];
            ar += r4.x * h0; az += z4.x * h0; an += n4.x * h0;
            ar += r4.y * h1; az += z4.y * h1; an += n4.y * h1;
            ar += r4.z * h2; az += z4.z * h2; an += n4.z * h2;
            ar += r4.w * h3; az += z4.w * h3; an += n4.w * h3;
        }
        ar += br; az += bz; an += bn;

        const float r = 1.0f / (1.0f + expf(-(ir + ar)));
        const float z = 1.0f / (1.0f + expf(-(iz + az)));
        const float n = tanhf(inn + r * an);
        const float hp = hs[j * BB + b];
        const float hn = (1.0f - z) * n + z * hp;

        hbuf[((size_t)((s + 1) & 1) * 2 + dir) * dslab + j * BB + b] = hn;

        __syncthreads();
        if (tid == 0) {
            __threadfence();
            const unsigned target = (unsigned)(NJB * (s + 1));
            unsigned arrived = atomicAdd(mycnt, 1u) + 1u;
            if (arrived == target) {
                asm volatile("st.release.gpu.global.u32 [%0], %1;"
                             :: "l"(myflag), "r"((unsigned)(s + 1)) : "memory");
            }
        }

        y[((size_t)t * BB + b) * 1024 + (size_t)dir * HH + j] = hn;
        if (s == TT - 1) {
            hid[((size_t)dir * BB + b) * HH + j] = hn;
        } else {
            const int tn = dir ? (TT - 2 - s) : (s + 1);
            ir  = __ldcg(gir + tn * BB);
            iz  = __ldcg(giz + tn * BB);
            inn = __ldcg(gin + tn * BB);
            t = tn;
        }

        if (tid == 0) {
            unsigned v;
            do {
                asm volatile("ld.acquire.gpu.global.u32 %0, [%1];"
                             : "=r"(v) : "l"(myflag) : "memory");
            } while (v < (unsigned)(s + 1));
            __threadfence();
        }
        __syncthreads();
    }
}

// ---------------------------------------------------------------------------
// Launch
// ---------------------------------------------------------------------------
extern "C" void kernel_launch(void* const* d_in, const int* in_sizes, int n_in,
                              void* d_out, int out_size)
{
    (void)in_sizes; (void)n_in; (void)out_size;

    const float* x     = (const float*)d_in[0];
    const float* Wih0f = (const float*)d_in[1];
    const float* Whh0f = (const float*)d_in[2];
    const float* bih0f = (const float*)d_in[3];
    const float* bhh0f = (const float*)d_in[4];
    const float* Wih0b = (const float*)d_in[5];
    const float* Whh0b = (const float*)d_in[6];
    const float* bih0b = (const float*)d_in[7];
    const float* bhh0b = (const float*)d_in[8];
    const float* Wih1f = (const float*)d_in[9];
    const float* Whh1f = (const float*)d_in[10];
    const float* bih1f = (const float*)d_in[11];
    const float* bhh1f = (const float*)d_in[12];
    const float* Wih1b = (const float*)d_in[13];
    const float* Whh1b = (const float*)d_in[14];
    const float* bih1b = (const float*)d_in[15];
    const float* bhh1b = (const float*)d_in[16];

    float* out = (float*)d_out;
    const size_t Y_ELEMS = (size_t)TT * BB * 1024;
    float* hid0 = out + Y_ELEMS;
    float* hid1 = out + Y_ELEMS + 2 * BB * HH;

    float* gi = nullptr; cudaGetSymbolAddress((void**)&gi, g_gi);
    float* y0 = nullptr; cudaGetSymbolAddress((void**)&y0, g_y0);
    float* hb = nullptr; cudaGetSymbolAddress((void**)&hb, g_h);
    unsigned* cnt  = nullptr; cudaGetSymbolAddress((void**)&cnt, g_cnt);
    unsigned* flag = nullptr; cudaGetSymbolAddress((void**)&flag, g_flag);
    __nv_bfloat16* wh = nullptr; cudaGetSymbolAddress((void**)&wh, g_wh);
    __nv_bfloat16* wl = nullptr; cudaGetSymbolAddress((void**)&wl, g_wl);
    __nv_bfloat16* xh = nullptr; cudaGetSymbolAddress((void**)&xh, g_xh);
    __nv_bfloat16* xl = nullptr; cudaGetSymbolAddress((void**)&xl, g_xl);

    cudaFuncSetAttribute(gru_layer_persistent,
                         cudaFuncAttributeMaxDynamicSharedMemorySize, STEP_SMEM);

    const size_t M = (size_t)TT * BB;            // 16384
    const size_t DIROFF = (size_t)1536 * M;
    const size_t WSLAB = (size_t)1536 * 1024;    // per-dir W slab (bf16 elems)
    const dim3 ggrid(128, 12);                   // (m-tiles, n-tiles)

    // ---------------- layer 0 (K = 512) ----------------
    split_bf16<<<512, 256>>>(Wih0f, wh,          wl,          (size_t)1536 * DD);
    split_bf16<<<512, 256>>>(Wih0b, wh + WSLAB,  wl + WSLAB,  (size_t)1536 * DD);
    split_bf16<<<1024, 256>>>(x,    xh,          xl,          M * DD);

    gemm_bf16_mma<<<ggrid, 256>>>(wh,         wl,         xh, xl, bih0f,
                                  gi,          DD, (int)M);
    gemm_bf16_mma<<<ggrid, 256>>>(wh + WSLAB, wl + WSLAB, xh, xl, bih0b,
                                  gi + DIROFF, DD, (int)M);

    cudaMemsetAsync(hb, 0, (size_t)2 * HH * BB * sizeof(float));
    cudaMemsetAsync(cnt, 0, 2 * sizeof(unsigned));
    cudaMemsetAsync(flag, 0, 2 * sizeof(unsigned));

    gru_layer_persistent<<<2 * NJB, 256, STEP_SMEM>>>(
        gi, Whh0f, Whh0b, bhh0f, bhh0b, hb, cnt, flag, y0, hid0);

    // ---------------- layer 1 (K = 1024) ----------------
    split_bf16<<<512, 256>>>(Wih1f, wh,          wl,          (size_t)1536 * 1024);
    split_bf16<<<512, 256>>>(Wih1b, wh + WSLAB,  wl + WSLAB,  (size_t)1536 * 1024);
    split_bf16<<<1024, 256>>>(y0,   xh,          xl,          M * 1024);

    gemm_bf16_mma<<<ggrid, 256>>>(wh,         wl,         xh, xl, bih1f,
                                  gi,          1024, (int)M);
    gemm_bf16_mma<<<ggrid, 256>>>(wh + WSLAB, wl + WSLAB, xh, xl, bih1b,
                                  gi + DIROFF, 1024, (int)M);

    cudaMemsetAsync(hb, 0, (size_t)2 * HH * BB * sizeof(float));
    cudaMemsetAsync(cnt, 0, 2 * sizeof(unsigned));
    cudaMemsetAsync(flag, 0, 2 * sizeof(unsigned));

    gru_layer_persistent<<<2 * NJB, 256, STEP_SMEM>>>(
        gi, Whh1f, Whh1b, bhh1f, bhh1b, hb, cnt, flag, out, hid1);
}

// round 7
// speedup vs baseline: 1.8462x; 1.4333x over previous
#include <cuda_runtime.h>
#include <cuda_bf16.h>
#include <cstdint>
#include <cstddef>

typedef unsigned long long ull;

// Problem constants
#define TT 512
#define BB 32
#define DD 512
#define HH 512

// ---------------------------------------------------------------------------
// Scratch (device globals — no allocations allowed)
// ---------------------------------------------------------------------------
// gi TRANSPOSED: [dir][gate*512+j][t*32+b]  (m = t*32+b contiguous, ld = 16384)
__device__ float g_gi[(size_t)2 * 1536 * (TT * BB)];
// layer-0 output: [T][B][1024]
__device__ float g_y0[(size_t)TT * BB * 1024];
// hidden state bf16 hi/lo ping-pong: [2 buf][2 dir][32 b][512 k]
__device__ __nv_bfloat16 g_hh[2 * 2 * BB * HH];
__device__ __nv_bfloat16 g_hl[2 * 2 * BB * HH];
// barrier state
__device__ unsigned g_cnt[2];
__device__ unsigned g_flag[2];
// bf16 split operands (hi/lo) for tensor-core GEMMs
__device__ __nv_bfloat16 g_wh[2][1536 * 1024];        // W hi, per dir
__device__ __nv_bfloat16 g_wl[2][1536 * 1024];        // W lo, per dir
__device__ __nv_bfloat16 g_xh[(size_t)16384 * 1024];  // X hi
__device__ __nv_bfloat16 g_xl[(size_t)16384 * 1024];  // X lo

// ---------------------------------------------------------------------------
// MMA / ldmatrix macros (validated in round-6 GEMM)
// ---------------------------------------------------------------------------
#define MMA_BF16(d, a, b) \
    asm volatile("mma.sync.aligned.m16n8k16.row.col.f32.bf16.bf16.f32 " \
        "{%0,%1,%2,%3}, {%4,%5,%6,%7}, {%8,%9}, {%0,%1,%2,%3};" \
        : "+f"((d)[0]), "+f"((d)[1]), "+f"((d)[2]), "+f"((d)[3]) \
        : "r"((a)[0]), "r"((a)[1]), "r"((a)[2]), "r"((a)[3]), \
          "r"((b)[0]), "r"((b)[1]))

#define LDSM_X4(r, addr) \
    asm volatile("ldmatrix.sync.aligned.m8n8.x4.shared.b16 {%0,%1,%2,%3}, [%4];" \
        : "=r"((r)[0]), "=r"((r)[1]), "=r"((r)[2]), "=r"((r)[3]) : "r"(addr))

#define LDSM_X2(r, addr) \
    asm volatile("ldmatrix.sync.aligned.m8n8.x2.shared.b16 {%0,%1}, [%2];" \
        : "=r"((r)[0]), "=r"((r)[1]) : "r"(addr))

// ---------------------------------------------------------------------------
// split fp32 -> bf16 hi + bf16 lo
// ---------------------------------------------------------------------------
__global__ void split_bf16(const float* __restrict__ x,
                           __nv_bfloat16* __restrict__ hi,
                           __nv_bfloat16* __restrict__ lo, size_t n)
{
    size_t i = (size_t)blockIdx.x * blockDim.x + threadIdx.x;
    size_t stride = (size_t)gridDim.x * blockDim.x;
    for (; i < n; i += stride) {
        float v = x[i];
        __nv_bfloat16 h = __float2bfloat16(v);
        hi[i] = h;
        lo[i] = __float2bfloat16(v - __bfloat162float(h));
    }
}

// ---------------------------------------------------------------------------
// bf16 mma.sync GEMM, 3-pass hi/lo split (unchanged, round-6 passing).
// ---------------------------------------------------------------------------
#define SKW 40

__global__ void __launch_bounds__(256)
gemm_bf16_mma(const __nv_bfloat16* __restrict__ Wh,
              const __nv_bfloat16* __restrict__ Wl,
              const __nv_bfloat16* __restrict__ Xh,
              const __nv_bfloat16* __restrict__ Xl,
              const float* __restrict__ bias,
              float* __restrict__ C, int K, int ldc)
{
    __shared__ __align__(16) __nv_bfloat16 sWh[128 * SKW];
    __shared__ __align__(16) __nv_bfloat16 sWl[128 * SKW];
    __shared__ __align__(16) __nv_bfloat16 sXh[128 * SKW];
    __shared__ __align__(16) __nv_bfloat16 sXl[128 * SKW];

    const int tid  = threadIdx.x;
    const int wid  = tid >> 5;
    const int lane = tid & 31;
    const int m0   = blockIdx.x * 128;
    const int n0   = blockIdx.y * 128;
    const int wn   = wid >> 2;   // 0..1 (n)
    const int wm   = wid & 3;    // 0..3 (m)

    float acc[4][4][4];
#pragma unroll
    for (int nt = 0; nt < 4; nt++)
#pragma unroll
        for (int mt = 0; mt < 4; mt++)
#pragma unroll
            for (int e = 0; e < 4; e++) acc[nt][mt][e] = 0.0f;

    const int a_row = wn * 64 + (lane & 15);
    const int a_col = (lane >> 4) * 8;
    const int b_row = wm * 32 + (lane & 7);
    const int b_col = ((lane >> 3) & 1) * 8;
    uint32_t aWh = (uint32_t)__cvta_generic_to_shared(&sWh[a_row * SKW + a_col]);
    uint32_t aWl = (uint32_t)__cvta_generic_to_shared(&sWl[a_row * SKW + a_col]);
    uint32_t aXh = (uint32_t)__cvta_generic_to_shared(&sXh[b_row * SKW + b_col]);
    uint32_t aXl = (uint32_t)__cvta_generic_to_shared(&sXl[b_row * SKW + b_col]);

    for (int k0 = 0; k0 < K; k0 += 32) {
#pragma unroll
        for (int i = 0; i < 2; i++) {
            int idx = tid + i * 256;       // 0..511
            int row = idx >> 2;
            int c   = idx & 3;
            int so  = row * SKW + c * 8;
            size_t gw = (size_t)(n0 + row) * K + k0 + c * 8;
            size_t gx = (size_t)(m0 + row) * K + k0 + c * 8;
            *(uint4*)&sWh[so] = *(const uint4*)(Wh + gw);
            *(uint4*)&sWl[so] = *(const uint4*)(Wl + gw);
            *(uint4*)&sXh[so] = *(const uint4*)(Xh + gx);
            *(uint4*)&sXl[so] = *(const uint4*)(Xl + gx);
        }
        __syncthreads();

#pragma unroll
        for (int kk = 0; kk < 2; kk++) {
            const uint32_t koff = (uint32_t)(kk * 16 * 2);  // bytes
            uint32_t ah[4][4], al[4][4], bh[4][2], bl[4][2];
#pragma unroll
            for (int nt = 0; nt < 4; nt++) {
                const uint32_t ro = (uint32_t)(nt * 16 * SKW * 2);
                LDSM_X4(ah[nt], aWh + ro + koff);
                LDSM_X4(al[nt], aWl + ro + koff);
            }
#pragma unroll
            for (int mt = 0; mt < 4; mt++) {
                const uint32_t ro = (uint32_t)(mt * 8 * SKW * 2);
                LDSM_X2(bh[mt], aXh + ro + koff);
                LDSM_X2(bl[mt], aXl + ro + koff);
            }
#pragma unroll
            for (int nt = 0; nt < 4; nt++)
#pragma unroll
                for (int mt = 0; mt < 4; mt++) {
                    MMA_BF16(acc[nt][mt], ah[nt], bh[mt]);
                    MMA_BF16(acc[nt][mt], ah[nt], bl[mt]);
                    MMA_BF16(acc[nt][mt], al[nt], bh[mt]);
                }
        }
        __syncthreads();
    }

    const int r0 = lane >> 2;
    const int c0 = (lane & 3) * 2;
#pragma unroll
    for (int nt = 0; nt < 4; nt++) {
        const int nbase = n0 + wn * 64 + nt * 16;
        const float b0 = bias[nbase + r0];
        const float b1 = bias[nbase + 8 + r0];
#pragma unroll
        for (int mt = 0; mt < 4; mt++) {
            const int mbase = m0 + wm * 32 + mt * 8;
            float2 v0, v1;
            v0.x = acc[nt][mt][0] + b0; v0.y = acc[nt][mt][1] + b0;
            v1.x = acc[nt][mt][2] + b1; v1.y = acc[nt][mt][3] + b1;
            *(float2*)(C + (size_t)(nbase + r0) * ldc + mbase + c0) = v0;
            *(float2*)(C + (size_t)(nbase + 8 + r0) * ldc + mbase + c0) = v1;
        }
    }
}

// ---------------------------------------------------------------------------
// Persistent MMA-based GRU layer kernel.
// Grid: 64 CTAs = 2 dirs x 32 j-blocks (16 j each). 128 threads (4 warps).
// Warp (wm, jh): m-tile wm (16 batch rows), j-half jh (8 j's), 3 gate n-tiles.
// D = h[32b x 512k] @ Whh[48n x 512k]^T via m16n8k16, 3-pass bf16 hi/lo.
// h carried in fp32 REGISTERS per owning lane; bf16 hi/lo published to global
// ping-pong for the next step's A operand. Whh hi/lo split staged in smem once.
// SMEM (bf16 elems, stride 520): Wh[48*520] Wl[48*520] Ah[32*520] Al[32*520]
//   = 166,400 B -> 1 CTA/SM, 64 CTAs co-resident (spin barrier safe).
// ---------------------------------------------------------------------------
#define RS 520
#define NCD 32   // CTAs per direction
#define MMA_SMEM ((2 * 48 * RS + 2 * 32 * RS) * 2)

__global__ __launch_bounds__(128, 1)
void gru_layer_mma(const float* __restrict__ gi,
                   const float* __restrict__ Whh_f,
                   const float* __restrict__ Whh_b,
                   const float* __restrict__ bhh_f,
                   const float* __restrict__ bhh_b,
                   __nv_bfloat16* __restrict__ hh,   // [2][2][32][512]
                   __nv_bfloat16* __restrict__ hl,
                   unsigned* __restrict__ cnt,
                   unsigned* __restrict__ flag,
                   float* __restrict__ y,            // [T][B][1024]
                   float* __restrict__ hid)          // [2][B][H]
{
    extern __shared__ __nv_bfloat16 smb[];
    __nv_bfloat16* sWh = smb;
    __nv_bfloat16* sWl = smb + 48 * RS;
    __nv_bfloat16* sAh = smb + 2 * 48 * RS;
    __nv_bfloat16* sAl = smb + 2 * 48 * RS + 32 * RS;

    const int tid  = threadIdx.x;
    const int wid  = tid >> 5;
    const int lane = tid & 31;
    const int dir  = blockIdx.x >> 5;
    const int j0   = (blockIdx.x & 31) * 16;

    const float* Whh = dir ? Whh_b : Whh_f;
    const float* bhh = dir ? bhh_b : bhh_f;

    // ---- stage Whh hi/lo split into smem once (48 rows x 512) ----
    // smem row rr = jh*24 + g*8 + jj  ->  global row g*512 + (j0 + jh*8 + jj)
    for (int i = tid; i < 48 * 128; i += 128) {
        int rr = i >> 7;
        int c4 = i & 127;
        int jh = rr / 24, rem = rr % 24;
        int g = rem >> 3, jj = rem & 7;
        int grow = g * 512 + j0 + jh * 8 + jj;
        float4 v = *(const float4*)(Whh + (size_t)grow * 512 + c4 * 4);
        int so = rr * RS + c4 * 4;
        float vv[4] = {v.x, v.y, v.z, v.w};
#pragma unroll
        for (int e = 0; e < 4; e++) {
            __nv_bfloat16 h = __float2bfloat16(vv[e]);
            sWh[so + e] = h;
            sWl[so + e] = __float2bfloat16(vv[e] - __bfloat162float(h));
        }
    }

    // ---- per-warp / per-lane geometry ----
    const int wm = wid & 1;        // m-tile (batch half)
    const int jh = wid >> 1;       // j-half
    const uint32_t aAh = (uint32_t)__cvta_generic_to_shared(
        sAh + (wm * 16 + (lane & 15)) * RS + (lane >> 4) * 8);
    const uint32_t aAl = (uint32_t)__cvta_generic_to_shared(
        sAl + (wm * 16 + (lane & 15)) * RS + (lane >> 4) * 8);
    uint32_t aBh[3], aBl[3];
#pragma unroll
    for (int g = 0; g < 3; g++) {
        int brow = jh * 24 + g * 8 + (lane & 7);
        int bcol = ((lane >> 3) & 1) * 8;
        aBh[g] = (uint32_t)__cvta_generic_to_shared(sWh + brow * RS + bcol);
        aBl[g] = (uint32_t)__cvta_generic_to_shared(sWl + brow * RS + bcol);
    }

    // D-fragment ownership: combos c: 0=(b0,j) 1=(b0,j+1) 2=(b1,j) 3=(b1,j+1)
    const int b0 = wm * 16 + (lane >> 2);
    const int b1 = b0 + 8;
    const int j  = j0 + jh * 8 + 2 * (lane & 3);

    const float br0 = bhh[j],            br1 = bhh[j + 1];
    const float bz0 = bhh[HH + j],       bz1 = bhh[HH + j + 1];
    const float bn0 = bhh[2 * HH + j],   bn1 = bhh[2 * HH + j + 1];

    // gi row bases for 3 gates x 2 j's
    const float* gb[3][2];
#pragma unroll
    for (int g = 0; g < 3; g++) {
#pragma unroll
        for (int q = 0; q < 2; q++)
            gb[g][q] = gi + ((size_t)dir * 1536 + g * 512 + j + q) * (size_t)(TT * BB);
    }

    unsigned* mycnt  = cnt + dir;
    unsigned* myflag = flag + dir;

    float hp[4] = {0.0f, 0.0f, 0.0f, 0.0f};

    for (int s = 0; s < TT; s++) {
        const int t = dir ? (TT - 1 - s) : s;

        // ---- stage A (h hi/lo) for this step: 32 rows x 512 bf16 each ----
        {
            const uint4* srch = (const uint4*)(hh + ((size_t)(s & 1) * 2 + dir) * (BB * HH));
            const uint4* srcl = (const uint4*)(hl + ((size_t)(s & 1) * 2 + dir) * (BB * HH));
#pragma unroll
            for (int i = 0; i < 16; i++) {
                int idx = tid + i * 128;      // 0..2047
                int row = idx >> 6;
                int c8  = idx & 63;
                uint4 vh = __ldcg(srch + idx);
                uint4 vl = __ldcg(srcl + idx);
                *(uint4*)(sAh + row * RS + c8 * 8) = vh;
                *(uint4*)(sAl + row * RS + c8 * 8) = vl;
            }
        }
        __syncthreads();

        // ---- prefetch gi for this step (consumed after the MMA loop) ----
        float pre[3][4];
#pragma unroll
        for (int g = 0; g < 3; g++) {
            pre[g][0] = __ldcg(gb[g][0] + t * BB + b0);
            pre[g][1] = __ldcg(gb[g][1] + t * BB + b0);
            pre[g][2] = __ldcg(gb[g][0] + t * BB + b1);
            pre[g][3] = __ldcg(gb[g][1] + t * BB + b1);
        }

        // ---- MMA: 32 ktiles x 3 gates x 3 passes ----
        float acc[3][4];
#pragma unroll
        for (int g = 0; g < 3; g++)
#pragma unroll
            for (int e = 0; e < 4; e++) acc[g][e] = 0.0f;

#pragma unroll 8
        for (int kt = 0; kt < 32; kt++) {
            const uint32_t koff = (uint32_t)(kt * 32);   // 16 bf16 = 32 B
            uint32_t ah[4], al[4];
            LDSM_X4(ah, aAh + koff);
            LDSM_X4(al, aAl + koff);
#pragma unroll
            for (int g = 0; g < 3; g++) {
                uint32_t bh[2], bl[2];
                LDSM_X2(bh, aBh[g] + koff);
                LDSM_X2(bl, aBl[g] + koff);
                MMA_BF16(acc[g], ah, bh);
                MMA_BF16(acc[g], ah, bl);
                MMA_BF16(acc[g], al, bh);
            }
        }

        // ---- gates + h update for 4 (b, j) combos ----
        float hn[4];
        const float brj[2] = {br0, br1}, bzj[2] = {bz0, bz1}, bnj[2] = {bn0, bn1};
#pragma unroll
        for (int c = 0; c < 4; c++) {
            const int q = c & 1;
            const float ar = acc[0][c] + brj[q];
            const float az = acc[1][c] + bzj[q];
            const float an = acc[2][c] + bnj[q];
            const float r = 1.0f / (1.0f + expf(-(pre[0][c] + ar)));
            const float z = 1.0f / (1.0f + expf(-(pre[1][c] + az)));
            const float n = tanhf(pre[2][c] + r * an);
            hn[c] = (1.0f - z) * n + z * hp[c];
            hp[c] = hn[c];
        }

        // ---- publish h (bf16 hi/lo, ping-pong) + y ----
        {
            const size_t ob = ((size_t)((s + 1) & 1) * 2 + dir) * (BB * HH);
            __nv_bfloat162 h2, l2;
            // (b0, j..j+1)
            h2.x = __float2bfloat16(hn[0]);
            h2.y = __float2bfloat16(hn[1]);
            l2.x = __float2bfloat16(hn[0] - __bfloat162float(h2.x));
            l2.y = __float2bfloat16(hn[1] - __bfloat162float(h2.y));
            *(__nv_bfloat162*)(hh + ob + (size_t)b0 * HH + j) = h2;
            *(__nv_bfloat162*)(hl + ob + (size_t)b0 * HH + j) = l2;
            // (b1, j..j+1)
            h2.x = __float2bfloat16(hn[2]);
            h2.y = __float2bfloat16(hn[3]);
            l2.x = __float2bfloat16(hn[2] - __bfloat162float(h2.x));
            l2.y = __float2bfloat16(hn[3] - __bfloat162float(h2.y));
            *(__nv_bfloat162*)(hh + ob + (size_t)b1 * HH + j) = h2;
            *(__nv_bfloat162*)(hl + ob + (size_t)b1 * HH + j) = l2;

            float2 y2;
            y2.x = hn[0]; y2.y = hn[1];
            *(float2*)(y + ((size_t)t * BB + b0) * 1024 + (size_t)dir * HH + j) = y2;
            y2.x = hn[2]; y2.y = hn[3];
            *(float2*)(y + ((size_t)t * BB + b1) * 1024 + (size_t)dir * HH + j) = y2;

            if (s == TT - 1) {
                float2 q2;
                q2.x = hn[0]; q2.y = hn[1];
                *(float2*)(hid + ((size_t)dir * BB + b0) * HH + j) = q2;
                q2.x = hn[2]; q2.y = hn[3];
                *(float2*)(hid + ((size_t)dir * BB + b1) * HH + j) = q2;
            }
        }

        // ---- per-direction grid barrier: counter + sense flag ----
        __syncthreads();
        if (tid == 0) {
            __threadfence();
            const unsigned target = (unsigned)(NCD * (s + 1));
            unsigned arrived = atomicAdd(mycnt, 1u) + 1u;
            if (arrived == target) {
                asm volatile("st.release.gpu.global.u32 [%0], %1;"
                             :: "l"(myflag), "r"((unsigned)(s + 1)) : "memory");
            } else {
                unsigned v;
                do {
                    asm volatile("ld.acquire.gpu.global.u32 %0, [%1];"
                                 : "=r"(v) : "l"(myflag) : "memory");
                } while (v < (unsigned)(s + 1));
            }
            __threadfence();
        }
        __syncthreads();
    }
}

// ---------------------------------------------------------------------------
// Launch
// ---------------------------------------------------------------------------
extern "C" void kernel_launch(void* const* d_in, const int* in_sizes, int n_in,
                              void* d_out, int out_size)
{
    (void)in_sizes; (void)n_in; (void)out_size;

    const float* x     = (const float*)d_in[0];
    const float* Wih0f = (const float*)d_in[1];
    const float* Whh0f = (const float*)d_in[2];
    const float* bih0f = (const float*)d_in[3];
    const float* bhh0f = (const float*)d_in[4];
    const float* Wih0b = (const float*)d_in[5];
    const float* Whh0b = (const float*)d_in[6];
    const float* bih0b = (const float*)d_in[7];
    const float* bhh0b = (const float*)d_in[8];
    const float* Wih1f = (const float*)d_in[9];
    const float* Whh1f = (const float*)d_in[10];
    const float* bih1f = (const float*)d_in[11];
    const float* bhh1f = (const float*)d_in[12];
    const float* Wih1b = (const float*)d_in[13];
    const float* Whh1b = (const float*)d_in[14];
    const float* bih1b = (const float*)d_in[15];
    const float* bhh1b = (const float*)d_in[16];

    float* out = (float*)d_out;
    const size_t Y_ELEMS = (size_t)TT * BB * 1024;
    float* hid0 = out + Y_ELEMS;
    float* hid1 = out + Y_ELEMS + 2 * BB * HH;

    float* gi = nullptr; cudaGetSymbolAddress((void**)&gi, g_gi);
    float* y0 = nullptr; cudaGetSymbolAddress((void**)&y0, g_y0);
    __nv_bfloat16* hh = nullptr; cudaGetSymbolAddress((void**)&hh, g_hh);
    __nv_bfloat16* hl = nullptr; cudaGetSymbolAddress((void**)&hl, g_hl);
    unsigned* cnt  = nullptr; cudaGetSymbolAddress((void**)&cnt, g_cnt);
    unsigned* flag = nullptr; cudaGetSymbolAddress((void**)&flag, g_flag);
    __nv_bfloat16* wh = nullptr; cudaGetSymbolAddress((void**)&wh, g_wh);
    __nv_bfloat16* wl = nullptr; cudaGetSymbolAddress((void**)&wl, g_wl);
    __nv_bfloat16* xh = nullptr; cudaGetSymbolAddress((void**)&xh, g_xh);
    __nv_bfloat16* xl = nullptr; cudaGetSymbolAddress((void**)&xl, g_xl);

    cudaFuncSetAttribute(gru_layer_mma,
                         cudaFuncAttributeMaxDynamicSharedMemorySize, MMA_SMEM);

    const size_t M = (size_t)TT * BB;            // 16384
    const size_t DIROFF = (size_t)1536 * M;
    const size_t WSLAB = (size_t)1536 * 1024;
    const dim3 ggrid(128, 12);                   // (m-tiles, n-tiles)
    const size_t HBYTES = (size_t)2 * 2 * BB * HH * sizeof(__nv_bfloat16);

    // ---------------- layer 0 (K = 512) ----------------
    split_bf16<<<512, 256>>>(Wih0f, wh,          wl,          (size_t)1536 * DD);
    split_bf16<<<512, 256>>>(Wih0b, wh + WSLAB,  wl + WSLAB,  (size_t)1536 * DD);
    split_bf16<<<1024, 256>>>(x,    xh,          xl,          M * DD);

    gemm_bf16_mma<<<ggrid, 256>>>(wh,         wl,         xh, xl, bih0f,
                                  gi,          DD, (int)M);
    gemm_bf16_mma<<<ggrid, 256>>>(wh + WSLAB, wl + WSLAB, xh, xl, bih0b,
                                  gi + DIROFF, DD, (int)M);

    cudaMemsetAsync(hh, 0, HBYTES);
    cudaMemsetAsync(hl, 0, HBYTES);
    cudaMemsetAsync(cnt, 0, 2 * sizeof(unsigned));
    cudaMemsetAsync(flag, 0, 2 * sizeof(unsigned));

    gru_layer_mma<<<2 * NCD, 128, MMA_SMEM>>>(
        gi, Whh0f, Whh0b, bhh0f, bhh0b, hh, hl, cnt, flag, y0, hid0);

    // ---------------- layer 1 (K = 1024) ----------------
    split_bf16<<<512, 256>>>(Wih1f, wh,          wl,          (size_t)1536 * 1024);
    split_bf16<<<512, 256>>>(Wih1b, wh + WSLAB,  wl + WSLAB,  (size_t)1536 * 1024);
    split_bf16<<<1024, 256>>>(y0,   xh,          xl,          M * 1024);

    gemm_bf16_mma<<<ggrid, 256>>>(wh,         wl,         xh, xl, bih1f,
                                  gi,          1024, (int)M);
    gemm_bf16_mma<<<ggrid, 256>>>(wh + WSLAB, wl + WSLAB, xh, xl, bih1b,
                                  gi + DIROFF, 1024, (int)M);

    cudaMemsetAsync(hh, 0, HBYTES);
    cudaMemsetAsync(hl, 0, HBYTES);
    cudaMemsetAsync(cnt, 0, 2 * sizeof(unsigned));
    cudaMemsetAsync(flag, 0, 2 * sizeof(unsigned));

    gru_layer_mma<<<2 * NCD, 128, MMA_SMEM>>>(
        gi, Whh1f, Whh1b, bhh1f, bhh1b, hh, hl, cnt, flag, out, hid1);
}

// round 8
// speedup vs baseline: 2.1162x; 1.1463x over previous
#include <cuda_runtime.h>
#include <cuda_bf16.h>
#include <cstdint>
#include <cstddef>

typedef unsigned long long ull;

// Problem constants
#define TT 512
#define BB 32
#define DD 512
#define HH 512

// ---------------------------------------------------------------------------
// Scratch (device globals — no allocations allowed)
// ---------------------------------------------------------------------------
__device__ float g_gi[(size_t)2 * 1536 * (TT * BB)];
__device__ float g_y0[(size_t)TT * BB * 1024];
// hidden state bf16 hi/lo ping-pong: [2 buf][2 dir][32 b][512 k]
__device__ __nv_bfloat16 g_hh[2 * 2 * BB * HH];
__device__ __nv_bfloat16 g_hl[2 * 2 * BB * HH];
__device__ unsigned g_cnt[2];
__device__ unsigned g_flag[2];
__device__ __nv_bfloat16 g_wh[2][1536 * 1024];
__device__ __nv_bfloat16 g_wl[2][1536 * 1024];
__device__ __nv_bfloat16 g_xh[(size_t)16384 * 1024];
__device__ __nv_bfloat16 g_xl[(size_t)16384 * 1024];

// ---------------------------------------------------------------------------
// MMA / ldmatrix macros
// ---------------------------------------------------------------------------
#define MMA_BF16(d, a, b) \
    asm volatile("mma.sync.aligned.m16n8k16.row.col.f32.bf16.bf16.f32 " \
        "{%0,%1,%2,%3}, {%4,%5,%6,%7}, {%8,%9}, {%0,%1,%2,%3};" \
        : "+f"((d)[0]), "+f"((d)[1]), "+f"((d)[2]), "+f"((d)[3]) \
        : "r"((a)[0]), "r"((a)[1]), "r"((a)[2]), "r"((a)[3]), \
          "r"((b)[0]), "r"((b)[1]))

#define LDSM_X4(r, addr) \
    asm volatile("ldmatrix.sync.aligned.m8n8.x4.shared.b16 {%0,%1,%2,%3}, [%4];" \
        : "=r"((r)[0]), "=r"((r)[1]), "=r"((r)[2]), "=r"((r)[3]) : "r"(addr))

#define LDSM_X2(r, addr) \
    asm volatile("ldmatrix.sync.aligned.m8n8.x2.shared.b16 {%0,%1}, [%2];" \
        : "=r"((r)[0]), "=r"((r)[1]) : "r"(addr))

// ---------------------------------------------------------------------------
// split fp32 -> bf16 hi + bf16 lo
// ---------------------------------------------------------------------------
__global__ void split_bf16(const float* __restrict__ x,
                           __nv_bfloat16* __restrict__ hi,
                           __nv_bfloat16* __restrict__ lo, size_t n)
{
    size_t i = (size_t)blockIdx.x * blockDim.x + threadIdx.x;
    size_t stride = (size_t)gridDim.x * blockDim.x;
    for (; i < n; i += stride) {
        float v = x[i];
        __nv_bfloat16 h = __float2bfloat16(v);
        hi[i] = h;
        lo[i] = __float2bfloat16(v - __bfloat162float(h));
    }
}

// ---------------------------------------------------------------------------
// bf16 mma.sync GEMM, 3-pass hi/lo split (unchanged, round-6/7 passing).
// ---------------------------------------------------------------------------
#define SKW 40

__global__ void __launch_bounds__(256)
gemm_bf16_mma(const __nv_bfloat16* __restrict__ Wh,
              const __nv_bfloat16* __restrict__ Wl,
              const __nv_bfloat16* __restrict__ Xh,
              const __nv_bfloat16* __restrict__ Xl,
              const float* __restrict__ bias,
              float* __restrict__ C, int K, int ldc)
{
    __shared__ __align__(16) __nv_bfloat16 sWh[128 * SKW];
    __shared__ __align__(16) __nv_bfloat16 sWl[128 * SKW];
    __shared__ __align__(16) __nv_bfloat16 sXh[128 * SKW];
    __shared__ __align__(16) __nv_bfloat16 sXl[128 * SKW];

    const int tid  = threadIdx.x;
    const int wid  = tid >> 5;
    const int lane = tid & 31;
    const int m0   = blockIdx.x * 128;
    const int n0   = blockIdx.y * 128;
    const int wn   = wid >> 2;
    const int wm   = wid & 3;

    float acc[4][4][4];
#pragma unroll
    for (int nt = 0; nt < 4; nt++)
#pragma unroll
        for (int mt = 0; mt < 4; mt++)
#pragma unroll
            for (int e = 0; e < 4; e++) acc[nt][mt][e] = 0.0f;

    const int a_row = wn * 64 + (lane & 15);
    const int a_col = (lane >> 4) * 8;
    const int b_row = wm * 32 + (lane & 7);
    const int b_col = ((lane >> 3) & 1) * 8;
    uint32_t aWh = (uint32_t)__cvta_generic_to_shared(&sWh[a_row * SKW + a_col]);
    uint32_t aWl = (uint32_t)__cvta_generic_to_shared(&sWl[a_row * SKW + a_col]);
    uint32_t aXh = (uint32_t)__cvta_generic_to_shared(&sXh[b_row * SKW + b_col]);
    uint32_t aXl = (uint32_t)__cvta_generic_to_shared(&sXl[b_row * SKW + b_col]);

    for (int k0 = 0; k0 < K; k0 += 32) {
#pragma unroll
        for (int i = 0; i < 2; i++) {
            int idx = tid + i * 256;
            int row = idx >> 2;
            int c   = idx & 3;
            int so  = row * SKW + c * 8;
            size_t gw = (size_t)(n0 + row) * K + k0 + c * 8;
            size_t gx = (size_t)(m0 + row) * K + k0 + c * 8;
            *(uint4*)&sWh[so] = *(const uint4*)(Wh + gw);
            *(uint4*)&sWl[so] = *(const uint4*)(Wl + gw);
            *(uint4*)&sXh[so] = *(const uint4*)(Xh + gx);
            *(uint4*)&sXl[so] = *(const uint4*)(Xl + gx);
        }
        __syncthreads();

#pragma unroll
        for (int kk = 0; kk < 2; kk++) {
            const uint32_t koff = (uint32_t)(kk * 16 * 2);
            uint32_t ah[4][4], al[4][4], bh[4][2], bl[4][2];
#pragma unroll
            for (int nt = 0; nt < 4; nt++) {
                const uint32_t ro = (uint32_t)(nt * 16 * SKW * 2);
                LDSM_X4(ah[nt], aWh + ro + koff);
                LDSM_X4(al[nt], aWl + ro + koff);
            }
#pragma unroll
            for (int mt = 0; mt < 4; mt++) {
                const uint32_t ro = (uint32_t)(mt * 8 * SKW * 2);
                LDSM_X2(bh[mt], aXh + ro + koff);
                LDSM_X2(bl[mt], aXl + ro + koff);
            }
#pragma unroll
            for (int nt = 0; nt < 4; nt++)
#pragma unroll
                for (int mt = 0; mt < 4; mt++) {
                    MMA_BF16(acc[nt][mt], ah[nt], bh[mt]);
                    MMA_BF16(acc[nt][mt], ah[nt], bl[mt]);
                    MMA_BF16(acc[nt][mt], al[nt], bh[mt]);
                }
        }
        __syncthreads();
    }

    const int r0 = lane >> 2;
    const int c0 = (lane & 3) * 2;
#pragma unroll
    for (int nt = 0; nt < 4; nt++) {
        const int nbase = n0 + wn * 64 + nt * 16;
        const float b0 = bias[nbase + r0];
        const float b1 = bias[nbase + 8 + r0];
#pragma unroll
        for (int mt = 0; mt < 4; mt++) {
            const int mbase = m0 + wm * 32 + mt * 8;
            float2 v0, v1;
            v0.x = acc[nt][mt][0] + b0; v0.y = acc[nt][mt][1] + b0;
            v1.x = acc[nt][mt][2] + b1; v1.y = acc[nt][mt][3] + b1;
            *(float2*)(C + (size_t)(nbase + r0) * ldc + mbase + c0) = v0;
            *(float2*)(C + (size_t)(nbase + 8 + r0) * ldc + mbase + c0) = v1;
        }
    }
}

// ---------------------------------------------------------------------------
// Persistent MMA GRU, v2: register-resident Whh fragments + k-specialized warps.
// Grid: 128 CTAs = 2 dirs x 64 j-blocks (8 j each). 128 threads (4 warps).
// Warp w owns K-quarter [w*128, (w+1)*128) = 8 ktiles; holds B frags for
// 3 gates x 8 kt x (hi,lo) in 96 registers, loaded once.
// Per step: stage h hi/lo to smem, A-ldmatrix only, 144 MMAs/warp,
// cross-warp K-reduction via smem, warps 0/1 do gates for m-tile 0/1.
// SMEM: A 2x32x520x2B = 66,560 + red 12,288 = 78,848 B (W init tile aliased).
// 1 CTA/SM, 128 <= 148 SMs co-resident (spin barrier safe).
// ---------------------------------------------------------------------------
#define RS 520
#define NCD 64   // CTAs per direction
#define A_ELEMS (32 * RS)
#define RED_OFF (2 * A_ELEMS * 2)                   // byte offset of red buffer
#define MMA_SMEM (RED_OFF + 4 * 2 * 3 * 32 * 16)    // + red[4][2][3][32] float4

__global__ __launch_bounds__(128, 1)
void gru_layer_mma(const float* __restrict__ gi,
                   const float* __restrict__ Whh_f,
                   const float* __restrict__ Whh_b,
                   const float* __restrict__ bhh_f,
                   const float* __restrict__ bhh_b,
                   __nv_bfloat16* __restrict__ hh,   // [2][2][32][512]
                   __nv_bfloat16* __restrict__ hl,
                   unsigned* __restrict__ cnt,
                   unsigned* __restrict__ flag,
                   float* __restrict__ y,            // [T][B][1024]
                   float* __restrict__ hid)          // [2][B][H]
{
    extern __shared__ __align__(16) char smraw[];
    __nv_bfloat16* sAh = (__nv_bfloat16*)smraw;
    __nv_bfloat16* sAl = sAh + A_ELEMS;
    float* red = (float*)(smraw + RED_OFF);          // [w][mt][g][lane][4]

    // W init tile aliases the A region (24 rows x RS, hi then lo)
    __nv_bfloat16* sWh = sAh;
    __nv_bfloat16* sWl = sAh + 24 * RS;

    const int tid  = threadIdx.x;
    const int wid  = tid >> 5;
    const int lane = tid & 31;
    const int dir  = (int)(blockIdx.x >> 6);
    const int j0   = (int)(blockIdx.x & 63) * 8;

    const float* Whh = dir ? Whh_b : Whh_f;
    const float* bhh = dir ? bhh_b : bhh_f;

    // ---- stage Whh tile (24 rows x 512) hi/lo split into smem ----
    for (int i = tid; i < 24 * 128; i += 128) {
        int rr = i >> 7;          // 0..23  (= g*8 + jj)
        int c4 = i & 127;
        int g = rr >> 3, jj = rr & 7;
        int grow = g * 512 + j0 + jj;
        float4 v = *(const float4*)(Whh + (size_t)grow * 512 + c4 * 4);
        int so = rr * RS + c4 * 4;
        float vv[4] = {v.x, v.y, v.z, v.w};
#pragma unroll
        for (int e = 0; e < 4; e++) {
            __nv_bfloat16 h = __float2bfloat16(vv[e]);
            sWh[so + e] = h;
            sWl[so + e] = __float2bfloat16(vv[e] - __bfloat162float(h));
        }
    }
    __syncthreads();

    // ---- hoist B fragments into registers: [8 kt][3 g][hi/lo][2] ----
    uint32_t bh[8][3][2], bl[8][3][2];
    {
        const int brow = (lane & 7);
        const int bcol = ((lane >> 3) & 1) * 8;
#pragma unroll
        for (int kt = 0; kt < 8; kt++) {
            const uint32_t koff = (uint32_t)((wid * 8 + kt) * 16 * 2);
#pragma unroll
            for (int g = 0; g < 3; g++) {
                uint32_t ah_ = (uint32_t)__cvta_generic_to_shared(
                    sWh + (g * 8 + brow) * RS + bcol) + koff;
                uint32_t al_ = (uint32_t)__cvta_generic_to_shared(
                    sWl + (g * 8 + brow) * RS + bcol) + koff;
                LDSM_X2(bh[kt][g], ah_);
                LDSM_X2(bl[kt][g], al_);
            }
        }
    }
    __syncthreads();   // W region dead; A buffers may now be written

    // ---- per-lane geometry ----
    // A ldmatrix base (per m-tile), k advanced per ktile
    uint32_t aAh[2], aAl[2];
#pragma unroll
    for (int mt = 0; mt < 2; mt++) {
        const int arow = mt * 16 + (lane & 15);
        const int acol = (lane >> 4) * 8;
        aAh[mt] = (uint32_t)__cvta_generic_to_shared(sAh + arow * RS + acol);
        aAl[mt] = (uint32_t)__cvta_generic_to_shared(sAl + arow * RS + acol);
    }

    // gates ownership (warps 0/1 only): mt = wid
    const int gm  = wid;                       // m-tile for gate phase
    const int b0  = gm * 16 + (lane >> 2);
    const int b1  = b0 + 8;
    const int j   = j0 + 2 * (lane & 3);

    const float br0 = bhh[j],          br1 = bhh[j + 1];
    const float bz0 = bhh[HH + j],     bz1 = bhh[HH + j + 1];
    const float bn0 = bhh[2 * HH + j], bn1 = bhh[2 * HH + j + 1];

    const float* gb[3][2];
#pragma unroll
    for (int g = 0; g < 3; g++) {
#pragma unroll
        for (int q = 0; q < 2; q++)
            gb[g][q] = gi + ((size_t)dir * 1536 + g * 512 + j + q) * (size_t)(TT * BB);
    }

    unsigned* mycnt  = cnt + dir;
    unsigned* myflag = flag + dir;

    float hp[4] = {0.0f, 0.0f, 0.0f, 0.0f};

    for (int s = 0; s < TT; s++) {
        const int t = dir ? (TT - 1 - s) : s;

        // ---- stage h hi/lo for this step: 32 rows x 512 bf16 each ----
        {
            const uint4* srch = (const uint4*)(hh + ((size_t)(s & 1) * 2 + dir) * (BB * HH));
            const uint4* srcl = (const uint4*)(hl + ((size_t)(s & 1) * 2 + dir) * (BB * HH));
#pragma unroll
            for (int i = 0; i < 16; i++) {
                int idx = tid + i * 128;      // 0..2047
                int row = idx >> 6;
                int c8  = idx & 63;
                uint4 vh = __ldcg(srch + idx);
                uint4 vl = __ldcg(srcl + idx);
                *(uint4*)(sAh + row * RS + c8 * 8) = vh;
                *(uint4*)(sAl + row * RS + c8 * 8) = vl;
            }
        }
        __syncthreads();

        // ---- prefetch gi (warps 0/1) ----
        float pre[3][4];
        if (wid < 2) {
#pragma unroll
            for (int g = 0; g < 3; g++) {
                pre[g][0] = __ldcg(gb[g][0] + t * BB + b0);
                pre[g][1] = __ldcg(gb[g][1] + t * BB + b0);
                pre[g][2] = __ldcg(gb[g][0] + t * BB + b1);
                pre[g][3] = __ldcg(gb[g][1] + t * BB + b1);
            }
        }

        // ---- MMA over this warp's 8 ktiles ----
        float acc[2][3][4];
#pragma unroll
        for (int mt = 0; mt < 2; mt++)
#pragma unroll
            for (int g = 0; g < 3; g++)
#pragma unroll
                for (int e = 0; e < 4; e++) acc[mt][g][e] = 0.0f;

#pragma unroll
        for (int kt = 0; kt < 8; kt++) {
            const uint32_t koff = (uint32_t)((wid * 8 + kt) * 32);  // bytes
#pragma unroll
            for (int mt = 0; mt < 2; mt++) {
                uint32_t ah[4], al[4];
                LDSM_X4(ah, aAh[mt] + koff);
                LDSM_X4(al, aAl[mt] + koff);
#pragma unroll
                for (int g = 0; g < 3; g++) {
                    MMA_BF16(acc[mt][g], ah, bh[kt][g]);
                    MMA_BF16(acc[mt][g], ah, bl[kt][g]);
                    MMA_BF16(acc[mt][g], al, bh[kt][g]);
                }
            }
        }

        // ---- cross-warp K-reduction via smem ----
#pragma unroll
        for (int mt = 0; mt < 2; mt++)
#pragma unroll
            for (int g = 0; g < 3; g++) {
                float4 v;
                v.x = acc[mt][g][0]; v.y = acc[mt][g][1];
                v.z = acc[mt][g][2]; v.w = acc[mt][g][3];
                *(float4*)(red + (((wid * 2 + mt) * 3 + g) * 32 + lane) * 4) = v;
            }
        __syncthreads();

        // ---- gates (warps 0/1, m-tile = wid) ----
        if (wid < 2) {
            float tot[3][4];
#pragma unroll
            for (int g = 0; g < 3; g++) {
                float4 v0 = *(float4*)(red + (((0 * 2 + gm) * 3 + g) * 32 + lane) * 4);
                float4 v1 = *(float4*)(red + (((1 * 2 + gm) * 3 + g) * 32 + lane) * 4);
                float4 v2 = *(float4*)(red + (((2 * 2 + gm) * 3 + g) * 32 + lane) * 4);
                float4 v3 = *(float4*)(red + (((3 * 2 + gm) * 3 + g) * 32 + lane) * 4);
                tot[g][0] = ((v0.x + v1.x) + (v2.x + v3.x));
                tot[g][1] = ((v0.y + v1.y) + (v2.y + v3.y));
                tot[g][2] = ((v0.z + v1.z) + (v2.z + v3.z));
                tot[g][3] = ((v0.w + v1.w) + (v2.w + v3.w));
            }

            float hn[4];
            const float brj[2] = {br0, br1}, bzj[2] = {bz0, bz1}, bnj[2] = {bn0, bn1};
#pragma unroll
            for (int c = 0; c < 4; c++) {
                const int q = c & 1;
                const float ar = tot[0][c] + brj[q];
                const float az = tot[1][c] + bzj[q];
                const float an = tot[2][c] + bnj[q];
                const float r = 1.0f / (1.0f + expf(-(pre[0][c] + ar)));
                const float z = 1.0f / (1.0f + expf(-(pre[1][c] + az)));
                const float n = tanhf(pre[2][c] + r * an);
                hn[c] = (1.0f - z) * n + z * hp[c];
                hp[c] = hn[c];
            }

            // ---- publish h (bf16 hi/lo, ping-pong) + y ----
            const size_t ob = ((size_t)((s + 1) & 1) * 2 + dir) * (BB * HH);
            __nv_bfloat162 h2, l2;
            h2.x = __float2bfloat16(hn[0]);
            h2.y = __float2bfloat16(hn[1]);
            l2.x = __float2bfloat16(hn[0] - __bfloat162float(h2.x));
            l2.y = __float2bfloat16(hn[1] - __bfloat162float(h2.y));
            *(__nv_bfloat162*)(hh + ob + (size_t)b0 * HH + j) = h2;
            *(__nv_bfloat162*)(hl + ob + (size_t)b0 * HH + j) = l2;
            h2.x = __float2bfloat16(hn[2]);
            h2.y = __float2bfloat16(hn[3]);
            l2.x = __float2bfloat16(hn[2] - __bfloat162float(h2.x));
            l2.y = __float2bfloat16(hn[3] - __bfloat162float(h2.y));
            *(__nv_bfloat162*)(hh + ob + (size_t)b1 * HH + j) = h2;
            *(__nv_bfloat162*)(hl + ob + (size_t)b1 * HH + j) = l2;

            float2 y2;
            y2.x = hn[0]; y2.y = hn[1];
            *(float2*)(y + ((size_t)t * BB + b0) * 1024 + (size_t)dir * HH + j) = y2;
            y2.x = hn[2]; y2.y = hn[3];
            *(float2*)(y + ((size_t)t * BB + b1) * 1024 + (size_t)dir * HH + j) = y2;

            if (s == TT - 1) {
                float2 q2;
                q2.x = hn[0]; q2.y = hn[1];
                *(float2*)(hid + ((size_t)dir * BB + b0) * HH + j) = q2;
                q2.x = hn[2]; q2.y = hn[3];
                *(float2*)(hid + ((size_t)dir * BB + b1) * HH + j) = q2;
            }
        }

        // ---- per-direction grid barrier: counter + sense flag ----
        __syncthreads();
        if (tid == 0) {
            __threadfence();
            const unsigned target = (unsigned)(NCD * (s + 1));
            unsigned arrived = atomicAdd(mycnt, 1u) + 1u;
            if (arrived == target) {
                asm volatile("st.release.gpu.global.u32 [%0], %1;"
                             :: "l"(myflag), "r"((unsigned)(s + 1)) : "memory");
            } else {
                unsigned v;
                do {
                    asm volatile("ld.acquire.gpu.global.u32 %0, [%1];"
                                 : "=r"(v) : "l"(myflag) : "memory");
                } while (v < (unsigned)(s + 1));
            }
            __threadfence();
        }
        __syncthreads();
    }
}

// ---------------------------------------------------------------------------
// Launch
// ---------------------------------------------------------------------------
extern "C" void kernel_launch(void* const* d_in, const int* in_sizes, int n_in,
                              void* d_out, int out_size)
{
    (void)in_sizes; (void)n_in; (void)out_size;

    const float* x     = (const float*)d_in[0];
    const float* Wih0f = (const float*)d_in[1];
    const float* Whh0f = (const float*)d_in[2];
    const float* bih0f = (const float*)d_in[3];
    const float* bhh0f = (const float*)d_in[4];
    const float* Wih0b = (const float*)d_in[5];
    const float* Whh0b = (const float*)d_in[6];
    const float* bih0b = (const float*)d_in[7];
    const float* bhh0b = (const float*)d_in[8];
    const float* Wih1f = (const float*)d_in[9];
    const float* Whh1f = (const float*)d_in[10];
    const float* bih1f = (const float*)d_in[11];
    const float* bhh1f = (const float*)d_in[12];
    const float* Wih1b = (const float*)d_in[13];
    const float* Whh1b = (const float*)d_in[14];
    const float* bih1b = (const float*)d_in[15];
    const float* bhh1b = (const float*)d_in[16];

    float* out = (float*)d_out;
    const size_t Y_ELEMS = (size_t)TT * BB * 1024;
    float* hid0 = out + Y_ELEMS;
    float* hid1 = out + Y_ELEMS + 2 * BB * HH;

    float* gi = nullptr; cudaGetSymbolAddress((void**)&gi, g_gi);
    float* y0 = nullptr; cudaGetSymbolAddress((void**)&y0, g_y0);
    __nv_bfloat16* hh = nullptr; cudaGetSymbolAddress((void**)&hh, g_hh);
    __nv_bfloat16* hl = nullptr; cudaGetSymbolAddress((void**)&hl, g_hl);
    unsigned* cnt  = nullptr; cudaGetSymbolAddress((void**)&cnt, g_cnt);
    unsigned* flag = nullptr; cudaGetSymbolAddress((void**)&flag, g_flag);
    __nv_bfloat16* wh = nullptr; cudaGetSymbolAddress((void**)&wh, g_wh);
    __nv_bfloat16* wl = nullptr; cudaGetSymbolAddress((void**)&wl, g_wl);
    __nv_bfloat16* xh = nullptr; cudaGetSymbolAddress((void**)&xh, g_xh);
    __nv_bfloat16* xl = nullptr; cudaGetSymbolAddress((void**)&xl, g_xl);

    cudaFuncSetAttribute(gru_layer_mma,
                         cudaFuncAttributeMaxDynamicSharedMemorySize, MMA_SMEM);

    const size_t M = (size_t)TT * BB;            // 16384
    const size_t DIROFF = (size_t)1536 * M;
    const size_t WSLAB = (size_t)1536 * 1024;
    const dim3 ggrid(128, 12);
    const size_t HBYTES = (size_t)2 * 2 * BB * HH * sizeof(__nv_bfloat16);

    // ---------------- layer 0 (K = 512) ----------------
    split_bf16<<<512, 256>>>(Wih0f, wh,          wl,          (size_t)1536 * DD);
    split_bf16<<<512, 256>>>(Wih0b, wh + WSLAB,  wl + WSLAB,  (size_t)1536 * DD);
    split_bf16<<<1024, 256>>>(x,    xh,          xl,          M * DD);

    gemm_bf16_mma<<<ggrid, 256>>>(wh,         wl,         xh, xl, bih0f,
                                  gi,          DD, (int)M);
    gemm_bf16_mma<<<ggrid, 256>>>(wh + WSLAB, wl + WSLAB, xh, xl, bih0b,
                                  gi + DIROFF, DD, (int)M);

    cudaMemsetAsync(hh, 0, HBYTES);
    cudaMemsetAsync(hl, 0, HBYTES);
    cudaMemsetAsync(cnt, 0, 2 * sizeof(unsigned));
    cudaMemsetAsync(flag, 0, 2 * sizeof(unsigned));

    gru_layer_mma<<<2 * NCD, 128, MMA_SMEM>>>(
        gi, Whh0f, Whh0b, bhh0f, bhh0b, hh, hl, cnt, flag, y0, hid0);

    // ---------------- layer 1 (K = 1024) ----------------
    split_bf16<<<512, 256>>>(Wih1f, wh,          wl,          (size_t)1536 * 1024);
    split_bf16<<<512, 256>>>(Wih1b, wh + WSLAB,  wl + WSLAB,  (size_t)1536 * 1024);
    split_bf16<<<1024, 256>>>(y0,   xh,          xl,          M * 1024);

    gemm_bf16_mma<<<ggrid, 256>>>(wh,         wl,         xh, xl, bih1f,
                                  gi,          1024, (int)M);
    gemm_bf16_mma<<<ggrid, 256>>>(wh + WSLAB, wl + WSLAB, xh, xl, bih1b,
                                  gi + DIROFF, 1024, (int)M);

    cudaMemsetAsync(hh, 0, HBYTES);
    cudaMemsetAsync(hl, 0, HBYTES);
    cudaMemsetAsync(cnt, 0, 2 * sizeof(unsigned));
    cudaMemsetAsync(flag, 0, 2 * sizeof(unsigned));

    gru_layer_mma<<<2 * NCD, 128, MMA_SMEM>>>(
        gi, Whh1f, Whh1b, bhh1f, bhh1b, hh, hl, cnt, flag, out, hid1);
}